// round 2
// baseline (speedup 1.0000x reference)
#include <cuda_runtime.h>

// Problem shape (fixed by dataset): x [512,1024] f32, a,b [1024,64,1] f32, a0 [1] f32
// out [512,1024] f32.
#define BATCH 512
#define NP    1024
#define NK    64

// Scratch for the pa/pb GEMM results (device globals: allocation-free rule).
__device__ float g_pa[BATCH * NK];
__device__ float g_pb[BATCH * NK];

// ---------- packed f32x2 helpers (sm_103a FFMA2 path, PTX-only) ----------
__device__ __forceinline__ unsigned long long ffma2(unsigned long long a,
                                                    unsigned long long b,
                                                    unsigned long long c) {
    unsigned long long d;
    asm("fma.rn.f32x2 %0, %1, %2, %3;" : "=l"(d) : "l"(a), "l"(b), "l"(c));
    return d;
}
__device__ __forceinline__ unsigned long long fadd2(unsigned long long a,
                                                    unsigned long long b) {
    unsigned long long d;
    asm("add.rn.f32x2 %0, %1, %2;" : "=l"(d) : "l"(a), "l"(b));
    return d;
}
__device__ __forceinline__ unsigned long long pack2(float lo, float hi) {
    unsigned long long d;
    asm("mov.b64 %0, {%1, %2};"
        : "=l"(d) : "r"(__float_as_uint(lo)), "r"(__float_as_uint(hi)));
    return d;
}
__device__ __forceinline__ float2 unpack2(unsigned long long v) {
    unsigned lo, hi;
    asm("mov.b64 {%0, %1}, %2;" : "=r"(lo), "=r"(hi) : "l"(v));
    return make_float2(__uint_as_float(lo), __uint_as_float(hi));
}

// ============================================================================
// Kernel 1: pa[b,k] = sum_p x[b,p]*a[p,k]; pb likewise.
// Block handles 4 batch rows. 256 threads = 16 k-quads x 16 p-groups.
// x staged in smem pre-packed as (x,x) f32x2 so the mainloop is pure
// LDG.128(a,b) + LDS.64(x) + 16 FFMA2.
// ============================================================================
__global__ __launch_bounds__(256, 1)
void k_gemm(const float* __restrict__ x,
            const float* __restrict__ a,
            const float* __restrict__ b) {
    __shared__ unsigned long long smem_buf[4 * NP];  // 32KB; x-packed, then reused as reduction buf

    const int tid = threadIdx.x;
    const int kq  = tid & 15;   // k quad: covers k = 4*kq .. 4*kq+3
    const int g   = tid >> 4;   // p-group 0..15
    const int b0  = blockIdx.x * 4;

    // Stage x rows [4][1024], duplicated into f32x2 pairs.
    {
        const float4* x4 = (const float4*)(x + (size_t)b0 * NP);
        for (int t = tid; t < 1024; t += 256) {
            float4 v = x4[t];
            int i   = t >> 8;
            int pb0 = (t & 255) * 4;
            unsigned long long* dst = smem_buf + i * NP + pb0;
            dst[0] = pack2(v.x, v.x);
            dst[1] = pack2(v.y, v.y);
            dst[2] = pack2(v.z, v.z);
            dst[3] = pack2(v.w, v.w);
        }
    }
    __syncthreads();

    const ulonglong2* a2 = (const ulonglong2*)a;  // a[p*64+4kq..] as 2 packed pairs
    const ulonglong2* b2 = (const ulonglong2*)b;

    unsigned long long acc[4][4];
    #pragma unroll
    for (int i = 0; i < 4; i++)
        #pragma unroll
        for (int c = 0; c < 4; c++) acc[i][c] = 0ull;

    #pragma unroll 4
    for (int p = g; p < NP; p += 16) {
        ulonglong2 av = a2[p * 16 + kq];
        ulonglong2 bv = b2[p * 16 + kq];
        #pragma unroll
        for (int i = 0; i < 4; i++) {
            unsigned long long x2 = smem_buf[i * NP + p];
            acc[i][0] = ffma2(x2, av.x, acc[i][0]);  // pa k,k+1
            acc[i][1] = ffma2(x2, av.y, acc[i][1]);  // pa k+2,k+3
            acc[i][2] = ffma2(x2, bv.x, acc[i][2]);  // pb k,k+1
            acc[i][3] = ffma2(x2, bv.y, acc[i][3]);  // pb k+2,k+3
        }
    }

    __syncthreads();  // done reading x; reuse smem as reduction buffer

    // red[g][i][kq][c] : g*256 + i*64 + kq*4 + c
    unsigned long long* red = smem_buf;
    #pragma unroll
    for (int i = 0; i < 4; i++)
        #pragma unroll
        for (int c = 0; c < 4; c++)
            red[g * 256 + i * 64 + kq * 4 + c] = acc[i][c];
    __syncthreads();

    // One (i, kq, c) entry per thread; sum across 16 p-groups.
    const int i2  = tid >> 6;
    const int rem = tid & 63;   // = kq2*4 + c2
    unsigned long long v = red[i2 * 64 + rem];
    #pragma unroll
    for (int gg = 1; gg < 16; gg++)
        v = fadd2(v, red[gg * 256 + i2 * 64 + rem]);

    const int kq2 = rem >> 2;
    const int c2  = rem & 3;
    const int bb  = b0 + i2;
    float2 vv = unpack2(v);
    if (c2 < 2) {
        int k = 4 * kq2 + 2 * c2;
        *(float2*)&g_pa[bb * NK + k] = vv;
    } else {
        int k = 4 * kq2 + 2 * (c2 - 2);
        *(float2*)&g_pb[bb * NK + k] = vv;
    }
}

// ============================================================================
// Kernel 2: out[b,p] = a0/(2P) + sum_k pa[b,k]*cos(k*th) + pb[b,k]*sin(k*th),
// th = (2pi/P)*x[b,p].
//
// Sign-folded Chebyshev: h_k = (-1)^floor(k/2) (pattern + + - -), g_k = h_k*c_k
// satisfies  g_{k+1} = (-1)^k * 2*c1 * g_k + g_{k-1}  -- a pure FMA with a
// compile-time alternating constant (+2c1 / -2c1). Signs h_k are folded into
// the coefficients. Two chains anchored at k=0 and k=32 (h_{32+i} = h_i since
// 32 is even, so the fold is uniform) bound the error growth.
// One block per batch row, one thread per p. (cos,sin) packed in one f32x2.
// ============================================================================
__global__ __launch_bounds__(1024, 1)
void k_fourier(const float* __restrict__ x,
               const float* __restrict__ a0,
               float* __restrict__ out) {
    __shared__ unsigned long long s_e[NK];  // h_k * (pa_k, pb_k) packed

    const int b   = blockIdx.x;
    const int tid = threadIdx.x;

    if (tid < NK) {
        float pa = g_pa[b * NK + tid];
        float pb = g_pb[b * NK + tid];
        float sgn = ((tid >> 1) & 1) ? -1.0f : 1.0f;   // h_k = (-1)^floor(k/2)
        s_e[tid] = pack2(sgn * pa, sgn * pb);
    }
    __syncthreads();

    const float TWO_PI_OVER_P = 0.006135923151542565f;  // 2*pi/1024
    float xv = x[b * NP + tid];
    float th = TWO_PI_OVER_P * xv;

    float s1, c1, s32v, c32v;
    sincosf(th, &s1, &c1);
    sincosf(32.0f * th, &s32v, &c32v);

    float t2 = 2.0f * c1;
    unsigned long long p2 = pack2(t2, t2);    // +2*c1
    unsigned long long n2 = pack2(-t2, -t2);  // -2*c1

    // chain A: g_i = h_i*(cos(i*th), sin(i*th)),          i = 0..31
    // chain B: f_i = h_i*(cos((32+i)*th), sin((32+i)*th)), i = 0..31
    unsigned long long e_p = pack2(1.0f, 0.0f);   // g_0
    unsigned long long e_c = pack2(c1, s1);       // g_1  (h_1 = +1)
    float c33 = fmaf(c32v, c1, -s32v * s1);       // cos(33*th)
    float s33 = fmaf(s32v, c1,  c32v * s1);       // sin(33*th)
    unsigned long long f_p = pack2(c32v, s32v);   // f_0
    unsigned long long f_c = pack2(c33, s33);     // f_1

    // Two independent accumulator chains.
    unsigned long long sumE = 0ull, sumF = 0ull;
    sumE = ffma2(s_e[0], e_p, sumE);
    sumE = ffma2(s_e[1], e_c, sumE);
    sumF = ffma2(s_e[32], f_p, sumF);
    sumF = ffma2(s_e[33], f_c, sumF);

    #pragma unroll
    for (int i = 2; i < 32; i++) {
        // g_i = (-1)^{i-1} * 2c1 * g_{i-1} + g_{i-2}:
        //   i even -> constant = -2c1 ; i odd -> constant = +2c1
        unsigned long long cst = (i & 1) ? p2 : n2;
        unsigned long long e_n = ffma2(cst, e_c, e_p);
        unsigned long long f_n = ffma2(cst, f_c, f_p);
        sumE = ffma2(s_e[i],      e_n, sumE);
        sumF = ffma2(s_e[32 + i], f_n, sumF);
        e_p = e_c; e_c = e_n;
        f_p = f_c; f_c = f_n;
    }

    float2 sE = unpack2(sumE);
    float2 sF = unpack2(sumF);
    float res = (sE.x + sE.y) + (sF.x + sF.y)
              + a0[0] * (1.0f / (2.0f * (float)NP));
    out[b * NP + tid] = res;
}

extern "C" void kernel_launch(void* const* d_in, const int* in_sizes, int n_in,
                              void* d_out, int out_size) {
    const float* x  = (const float*)d_in[0];
    const float* a  = (const float*)d_in[1];
    const float* b  = (const float*)d_in[2];
    const float* a0 = (const float*)d_in[3];
    float* out = (float*)d_out;

    k_gemm<<<BATCH / 4, 256>>>(x, a, b);
    k_fourier<<<BATCH, 1024>>>(x, a0, out);
}

// round 3
// speedup vs baseline: 1.1156x; 1.1156x over previous
#include <cuda_runtime.h>

// Problem shape (fixed by dataset): x [512,1024] f32, a,b [1024,64,1] f32, a0 [1] f32
// out [512,1024] f32.
#define BATCH 512
#define NP    1024
#define NK    64

// Scratch for the pa/pb GEMM results (device globals: allocation-free rule).
__device__ float g_pa[BATCH * NK];
__device__ float g_pb[BATCH * NK];

// ---------- packed f32x2 helpers (sm_103a FFMA2 path, PTX-only) ----------
__device__ __forceinline__ unsigned long long ffma2(unsigned long long a,
                                                    unsigned long long b,
                                                    unsigned long long c) {
    unsigned long long d;
    asm("fma.rn.f32x2 %0, %1, %2, %3;" : "=l"(d) : "l"(a), "l"(b), "l"(c));
    return d;
}
__device__ __forceinline__ unsigned long long fadd2(unsigned long long a,
                                                    unsigned long long b) {
    unsigned long long d;
    asm("add.rn.f32x2 %0, %1, %2;" : "=l"(d) : "l"(a), "l"(b));
    return d;
}
__device__ __forceinline__ unsigned long long pack2(float lo, float hi) {
    unsigned long long d;
    asm("mov.b64 %0, {%1, %2};"
        : "=l"(d) : "r"(__float_as_uint(lo)), "r"(__float_as_uint(hi)));
    return d;
}
__device__ __forceinline__ float2 unpack2(unsigned long long v) {
    unsigned lo, hi;
    asm("mov.b64 {%0, %1}, %2;" : "=r"(lo), "=r"(hi) : "l"(v));
    return make_float2(__uint_as_float(lo), __uint_as_float(hi));
}

// ============================================================================
// Kernel 1: pa[b,k] = sum_p x[b,p]*a[p,k]; pb likewise.
//
// Grid = 32 b-tiles x 4 k-tiles = 128 blocks, 256 threads.
// Each block: 16 batch rows x 16 k values. a,b are read by only 32 b-tiles
// (vs 128 before) -> L2 traffic 64MB -> ~20MB.
// x staged TRANSPOSED in dynamic smem: sx[p][16 rows] (64KB), so 4 rows load
// as one LDS.128. Thread map: kq = tid&3 (4 k-quads), rg = (tid>>2)&3
// (4 rows each), pg = tid>>4 (16 p-groups). Inner loop:
//   2x LDG.128 (a,b quad) + 1x LDS.128 (4 x-values) + 16 FFMA2.
// ============================================================================
__global__ __launch_bounds__(256, 1)
void k_gemm(const float* __restrict__ x,
            const float* __restrict__ a,
            const float* __restrict__ b) {
    extern __shared__ float sx[];  // [1024][16] floats = 64KB; reused as red buf

    const int tid = threadIdx.x;
    const int bt  = blockIdx.x >> 2;
    const int kt  = blockIdx.x & 3;
    const int b0  = bt * 16;

    // ---- stage x transposed: sx[p*16 + r] = x[b0+r][p] ----
    {
        const int r  = tid & 15;
        const int p4 = tid >> 4;  // 0..15, each handles float4 idx p4+16j
        const float4* x4 = (const float4*)(x + (size_t)(b0 + r) * NP);
        #pragma unroll
        for (int j = 0; j < 16; j++) {
            int i4 = p4 + 16 * j;
            float4 v = x4[i4];
            int p = i4 * 4;
            sx[(p + 0) * 16 + r] = v.x;
            sx[(p + 1) * 16 + r] = v.y;
            sx[(p + 2) * 16 + r] = v.z;
            sx[(p + 3) * 16 + r] = v.w;
        }
    }
    __syncthreads();

    const int kq = tid & 3;         // k-quad within k-tile
    const int rg = (tid >> 2) & 3;  // row group (4 rows)
    const int pg = tid >> 4;        // p-group
    const int kcol = kt * 4 + kq;   // ulonglong2 column index in a/b row

    const ulonglong2* a2 = (const ulonglong2*)a;  // row stride: 16 ulonglong2
    const ulonglong2* b2 = (const ulonglong2*)b;

    unsigned long long acc[4][4];
    #pragma unroll
    for (int j = 0; j < 4; j++)
        #pragma unroll
        for (int c = 0; c < 4; c++) acc[j][c] = 0ull;

    const int rbase = rg * 4;
    #pragma unroll 4
    for (int p = pg; p < NP; p += 16) {
        ulonglong2 av = a2[p * 16 + kcol];
        ulonglong2 bv = b2[p * 16 + kcol];
        float4 xv = *(const float4*)&sx[p * 16 + rbase];
        unsigned long long x0 = pack2(xv.x, xv.x);
        unsigned long long x1 = pack2(xv.y, xv.y);
        unsigned long long x2 = pack2(xv.z, xv.z);
        unsigned long long x3 = pack2(xv.w, xv.w);
        acc[0][0] = ffma2(x0, av.x, acc[0][0]);
        acc[0][1] = ffma2(x0, av.y, acc[0][1]);
        acc[0][2] = ffma2(x0, bv.x, acc[0][2]);
        acc[0][3] = ffma2(x0, bv.y, acc[0][3]);
        acc[1][0] = ffma2(x1, av.x, acc[1][0]);
        acc[1][1] = ffma2(x1, av.y, acc[1][1]);
        acc[1][2] = ffma2(x1, bv.x, acc[1][2]);
        acc[1][3] = ffma2(x1, bv.y, acc[1][3]);
        acc[2][0] = ffma2(x2, av.x, acc[2][0]);
        acc[2][1] = ffma2(x2, av.y, acc[2][1]);
        acc[2][2] = ffma2(x2, bv.x, acc[2][2]);
        acc[2][3] = ffma2(x2, bv.y, acc[2][3]);
        acc[3][0] = ffma2(x3, av.x, acc[3][0]);
        acc[3][1] = ffma2(x3, av.y, acc[3][1]);
        acc[3][2] = ffma2(x3, bv.x, acc[3][2]);
        acc[3][3] = ffma2(x3, bv.y, acc[3][3]);
    }

    __syncthreads();  // done reading sx; reuse as reduction buffer

    // red[pg][local], local = r*16 + kq*4 + c,  r = row-in-tile 0..15
    unsigned long long* red = (unsigned long long*)sx;  // 16*256*8B = 32KB
    #pragma unroll
    for (int j = 0; j < 4; j++)
        #pragma unroll
        for (int c = 0; c < 4; c++)
            red[pg * 256 + (rbase + j) * 16 + kq * 4 + c] = acc[j][c];
    __syncthreads();

    // One local entry per thread; sum across 16 p-groups.
    unsigned long long v = red[tid];
    #pragma unroll
    for (int gg = 1; gg < 16; gg++)
        v = fadd2(v, red[gg * 256 + tid]);

    const int r2  = tid >> 4;
    const int kq2 = (tid >> 2) & 3;
    const int c2  = tid & 3;
    float2 vv = unpack2(v);
    const int bb = b0 + r2;
    const int k0 = kt * 16 + kq2 * 4;
    if (c2 < 2) {
        *(float2*)&g_pa[bb * NK + k0 + 2 * c2] = vv;
    } else {
        *(float2*)&g_pb[bb * NK + k0 + 2 * (c2 - 2)] = vv;
    }
}

// ============================================================================
// Kernel 2: out[b,p] = a0/(2P) + sum_k pa[b,k]*cos(k*th) + pb[b,k]*sin(k*th),
// th = (2pi/P)*x[b,p].
//
// Sign-folded Chebyshev: h_k = (-1)^floor(k/2) (pattern + + - -), g_k = h_k*c_k
// satisfies  g_{k+1} = (-1)^k * 2*c1 * g_k + g_{k-1}  -- pure FMA with a
// compile-time alternating constant. Two chains anchored at k=0 and k=32.
// __sincosf (MUFU) for anchors: |th| <= 0.04, |32th| <= 1.2 -> abs err ~4e-7,
// measured amplification is mild (rel_err ~5e-5 expected, threshold 1e-3).
// 512 threads/block, half a batch row each; 3 blocks/SM.
// ============================================================================
__global__ __launch_bounds__(512, 3)
void k_fourier(const float* __restrict__ x,
               const float* __restrict__ a0,
               float* __restrict__ out) {
    __shared__ unsigned long long s_e[NK];  // h_k * (pa_k, pb_k) packed

    const int b   = blockIdx.x >> 1;
    const int ph  = (blockIdx.x & 1) * 512;
    const int tid = threadIdx.x;

    if (tid < NK) {
        float pa = g_pa[b * NK + tid];
        float pb = g_pb[b * NK + tid];
        float sgn = ((tid >> 1) & 1) ? -1.0f : 1.0f;   // h_k = (-1)^floor(k/2)
        s_e[tid] = pack2(sgn * pa, sgn * pb);
    }
    __syncthreads();

    const float TWO_PI_OVER_P = 0.006135923151542565f;  // 2*pi/1024
    float xv = x[b * NP + ph + tid];
    float th = TWO_PI_OVER_P * xv;

    float s1, c1, s32v, c32v;
    __sincosf(th, &s1, &c1);
    __sincosf(32.0f * th, &s32v, &c32v);

    float t2 = 2.0f * c1;
    unsigned long long p2 = pack2(t2, t2);    // +2*c1
    unsigned long long n2 = pack2(-t2, -t2);  // -2*c1

    // chain A: g_i = h_i*(cos(i*th), sin(i*th)),          i = 0..31
    // chain B: f_i = h_i*(cos((32+i)*th), sin((32+i)*th)), i = 0..31
    unsigned long long e_p = pack2(1.0f, 0.0f);   // g_0
    unsigned long long e_c = pack2(c1, s1);       // g_1  (h_1 = +1)
    float c33 = fmaf(c32v, c1, -s32v * s1);       // cos(33*th)
    float s33 = fmaf(s32v, c1,  c32v * s1);       // sin(33*th)
    unsigned long long f_p = pack2(c32v, s32v);   // f_0
    unsigned long long f_c = pack2(c33, s33);     // f_1

    unsigned long long sumE = 0ull, sumF = 0ull;
    sumE = ffma2(s_e[0], e_p, sumE);
    sumE = ffma2(s_e[1], e_c, sumE);
    sumF = ffma2(s_e[32], f_p, sumF);
    sumF = ffma2(s_e[33], f_c, sumF);

    #pragma unroll
    for (int i = 2; i < 32; i++) {
        // g_i = (-1)^{i-1} * 2c1 * g_{i-1} + g_{i-2}
        unsigned long long cst = (i & 1) ? p2 : n2;
        unsigned long long e_n = ffma2(cst, e_c, e_p);
        unsigned long long f_n = ffma2(cst, f_c, f_p);
        sumE = ffma2(s_e[i],      e_n, sumE);
        sumF = ffma2(s_e[32 + i], f_n, sumF);
        e_p = e_c; e_c = e_n;
        f_p = f_c; f_c = f_n;
    }

    float2 sE = unpack2(sumE);
    float2 sF = unpack2(sumF);
    float res = (sE.x + sE.y) + (sF.x + sF.y)
              + a0[0] * (1.0f / (2.0f * (float)NP));
    out[b * NP + ph + tid] = res;
}

extern "C" void kernel_launch(void* const* d_in, const int* in_sizes, int n_in,
                              void* d_out, int out_size) {
    const float* x  = (const float*)d_in[0];
    const float* a  = (const float*)d_in[1];
    const float* b  = (const float*)d_in[2];
    const float* a0 = (const float*)d_in[3];
    float* out = (float*)d_out;

    // 64KB dynamic smem for the x stage buffer (above the 48KB static limit).
    cudaFuncSetAttribute(k_gemm, cudaFuncAttributeMaxDynamicSharedMemorySize,
                         64 * 1024);

    k_gemm<<<128, 256, 64 * 1024>>>(x, a, b);
    k_fourier<<<BATCH * 2, 512>>>(x, a0, out);
}

// round 4
// speedup vs baseline: 1.2250x; 1.0981x over previous
#include <cuda_runtime.h>

// Problem shape (fixed by dataset): x [512,1024] f32, a,b [1024,64,1] f32, a0 [1] f32
// out [512,1024] f32.
#define BATCH 512
#define NP    1024
#define NK    64

typedef unsigned long long u64;

// Scratch for the pa/pb GEMM results (device globals: allocation-free rule).
__device__ float g_pa[BATCH * NK];
__device__ float g_pb[BATCH * NK];

// ---------- packed f32x2 helpers (sm_103a FFMA2 path, PTX-only) ----------
__device__ __forceinline__ u64 ffma2(u64 a, u64 b, u64 c) {
    u64 d;
    asm("fma.rn.f32x2 %0, %1, %2, %3;" : "=l"(d) : "l"(a), "l"(b), "l"(c));
    return d;
}
__device__ __forceinline__ u64 fadd2(u64 a, u64 b) {
    u64 d;
    asm("add.rn.f32x2 %0, %1, %2;" : "=l"(d) : "l"(a), "l"(b));
    return d;
}
__device__ __forceinline__ u64 pack2(float lo, float hi) {
    u64 d;
    asm("mov.b64 %0, {%1, %2};"
        : "=l"(d) : "r"(__float_as_uint(lo)), "r"(__float_as_uint(hi)));
    return d;
}
__device__ __forceinline__ float2 unpack2(u64 v) {
    unsigned lo, hi;
    asm("mov.b64 {%0, %1}, %2;" : "=r"(lo), "=r"(hi) : "l"(v));
    return make_float2(__uint_as_float(lo), __uint_as_float(hi));
}

// ============================================================================
// Kernel 1: pa[b,k] = sum_p x[b,p]*a[p,k]; pb likewise.
//
// Grid = 32 b-tiles x 4 k-tiles = 128 blocks, 512 threads (16 warps/SM).
// Thread map: kq = tid&3 (k-quad), rg = (tid>>2)&3 (4 rows each),
// pg = tid>>4 (32 p-groups).
// x staged ROW-major in dynamic smem as (x,x) u64 pairs with row stride 1027
// (coalesced LDG stage; conflict-free LDS reads of 4 rows @ fixed p).
// Inner loop per p: 2x LDG.128 (a,b quad) + 4x LDS.64 (x rows) + 16 FFMA2.
// ============================================================================
#define SU_STRIDE 1027   // u64 units; 2*1027 mod 32 = 6 -> rows 4 apart hit distinct banks

__global__ __launch_bounds__(512, 1)
void k_gemm(const float* __restrict__ x,
            const float* __restrict__ a,
            const float* __restrict__ b) {
    extern __shared__ u64 su[];          // [16][SU_STRIDE] u64 = 131456 B; reused as red buf
    __shared__ u64 part[512];            // final reduction partials

    const int tid = threadIdx.x;
    const int bt  = blockIdx.x >> 2;
    const int kt  = blockIdx.x & 3;
    const int b0  = bt * 16;

    // ---- stage x row-major, duplicated: su[r*SU_STRIDE + p] = (x[b0+r][p], same) ----
    {
        const int r  = tid >> 5;         // warp id = row -> coalesced LDG
        const int pp = tid & 31;
        const float* xr = x + (size_t)(b0 + r) * NP;
        u64* dst = su + r * SU_STRIDE;
        #pragma unroll 8
        for (int j = 0; j < 32; j++) {
            int p = pp + 32 * j;
            float v = xr[p];
            dst[p] = pack2(v, v);        // STS.64, 2-way at worst
        }
    }
    __syncthreads();

    const int kq = tid & 3;              // k-quad within k-tile
    const int rg = (tid >> 2) & 3;       // row group (4 rows)
    const int pg = tid >> 4;             // p-group 0..31
    const int kcol  = kt * 4 + kq;       // ulonglong2 column index in a/b row
    const int rbase = rg * 4;

    const ulonglong2* a2 = (const ulonglong2*)a;  // row stride: 16 ulonglong2
    const ulonglong2* b2 = (const ulonglong2*)b;

    u64 acc[4][4];
    #pragma unroll
    for (int j = 0; j < 4; j++)
        #pragma unroll
        for (int c = 0; c < 4; c++) acc[j][c] = 0ull;

    #pragma unroll 4
    for (int p = pg; p < NP; p += 32) {
        ulonglong2 av = a2[p * 16 + kcol];
        ulonglong2 bv = b2[p * 16 + kcol];
        u64 x0 = su[(rbase + 0) * SU_STRIDE + p];
        u64 x1 = su[(rbase + 1) * SU_STRIDE + p];
        u64 x2 = su[(rbase + 2) * SU_STRIDE + p];
        u64 x3 = su[(rbase + 3) * SU_STRIDE + p];
        acc[0][0] = ffma2(x0, av.x, acc[0][0]);
        acc[0][1] = ffma2(x0, av.y, acc[0][1]);
        acc[0][2] = ffma2(x0, bv.x, acc[0][2]);
        acc[0][3] = ffma2(x0, bv.y, acc[0][3]);
        acc[1][0] = ffma2(x1, av.x, acc[1][0]);
        acc[1][1] = ffma2(x1, av.y, acc[1][1]);
        acc[1][2] = ffma2(x1, bv.x, acc[1][2]);
        acc[1][3] = ffma2(x1, bv.y, acc[1][3]);
        acc[2][0] = ffma2(x2, av.x, acc[2][0]);
        acc[2][1] = ffma2(x2, av.y, acc[2][1]);
        acc[2][2] = ffma2(x2, bv.x, acc[2][2]);
        acc[2][3] = ffma2(x2, bv.y, acc[2][3]);
        acc[3][0] = ffma2(x3, av.x, acc[3][0]);
        acc[3][1] = ffma2(x3, av.y, acc[3][1]);
        acc[3][2] = ffma2(x3, bv.x, acc[3][2]);
        acc[3][3] = ffma2(x3, bv.y, acc[3][3]);
    }

    __syncthreads();  // done reading su; reuse as reduction buffer

    // red[pg][local], local = r*16 + kq*4 + c  (r = row-in-tile 0..15)
    u64* red = su;    // 32*256*8B = 64KB of the 128KB buffer
    #pragma unroll
    for (int j = 0; j < 4; j++)
        #pragma unroll
        for (int c = 0; c < 4; c++)
            red[pg * 256 + (rbase + j) * 16 + kq * 4 + c] = acc[j][c];
    __syncthreads();

    // Each thread sums 16 of the 32 p-groups for one local entry.
    const int local = tid & 255;
    const int half  = tid >> 8;       // 0: groups 0..15, 1: groups 16..31
    u64 v = red[(half * 16) * 256 + local];
    #pragma unroll
    for (int gg = 1; gg < 16; gg++)
        v = fadd2(v, red[(half * 16 + gg) * 256 + local]);
    part[tid] = v;
    __syncthreads();

    if (tid < 256) {
        u64 w = fadd2(part[tid], part[tid + 256]);
        const int r2  = tid >> 4;
        const int kq2 = (tid >> 2) & 3;
        const int c2  = tid & 3;
        float2 vv = unpack2(w);
        const int bb = b0 + r2;
        const int k0 = kt * 16 + kq2 * 4;
        if (c2 < 2) {
            *(float2*)&g_pa[bb * NK + k0 + 2 * c2] = vv;
        } else {
            *(float2*)&g_pb[bb * NK + k0 + 2 * (c2 - 2)] = vv;
        }
    }
}

// ============================================================================
// Kernel 2: out[b,p] = a0/(2P) + sum_k pa[b,k]*cos(k*th) + pb[b,k]*sin(k*th),
// th = (2pi/P)*x[b,p].
//
// Sign-folded Chebyshev (h_k = (-1)^floor(k/2)):
//   g_{k+1} = (-1)^k * 2*c1 * g_k + g_{k-1}   (pure FFMA2, alternating const)
// Two chains anchored at k=0 and k=32; MUFU __sincosf anchors (passed R3 at
// rel_err 1.9e-5, threshold 1e-3).
// One block per batch row: 256 threads x 4 points each. The 2 coefficient
// LDS.64 per iteration feed 16 FFMA2 (4 points x 4), giving 16 independent
// FMA chains per thread.
// ============================================================================
__global__ __launch_bounds__(256, 2)
void k_fourier(const float* __restrict__ x,
               const float* __restrict__ a0,
               float* __restrict__ out) {
    __shared__ u64 s_e[NK];  // h_k * (pa_k, pb_k) packed

    const int b   = blockIdx.x;
    const int tid = threadIdx.x;

    if (tid < NK) {
        float pa = g_pa[b * NK + tid];
        float pb = g_pb[b * NK + tid];
        float sgn = ((tid >> 1) & 1) ? -1.0f : 1.0f;   // h_k = (-1)^floor(k/2)
        s_e[tid] = pack2(sgn * pa, sgn * pb);
    }
    __syncthreads();

    const float TWO_PI_OVER_P = 0.006135923151542565f;  // 2*pi/1024

    u64 eP[4], eC[4], fP[4], fC[4], sE[4], sF[4], P2[4], N2[4];

    u64 ce0 = s_e[0], ce1 = s_e[1], cf0 = s_e[32], cf1 = s_e[33];

    #pragma unroll
    for (int j = 0; j < 4; j++) {
        float xv = x[b * NP + tid + 256 * j];
        float th = TWO_PI_OVER_P * xv;
        float s1, c1, s32v, c32v;
        __sincosf(th, &s1, &c1);
        __sincosf(32.0f * th, &s32v, &c32v);

        float t2 = 2.0f * c1;
        P2[j] = pack2(t2, t2);
        N2[j] = pack2(-t2, -t2);

        eP[j] = pack2(1.0f, 0.0f);                 // g_0
        eC[j] = pack2(c1, s1);                     // g_1 (h_1 = +1)
        float c33 = fmaf(c32v, c1, -s32v * s1);
        float s33 = fmaf(s32v, c1,  c32v * s1);
        fP[j] = pack2(c32v, s32v);                 // f_0 (h_32 = +1)
        fC[j] = pack2(c33, s33);                   // f_1 (h_33 = +1)

        sE[j] = ffma2(ce0, eP[j], 0ull);
        sE[j] = ffma2(ce1, eC[j], sE[j]);
        sF[j] = ffma2(cf0, fP[j], 0ull);
        sF[j] = ffma2(cf1, fC[j], sF[j]);
    }

    #pragma unroll
    for (int i = 2; i < 32; i++) {
        u64 cE = s_e[i];
        u64 cF = s_e[32 + i];
        #pragma unroll
        for (int j = 0; j < 4; j++) {
            // g_i = (-1)^{i-1} * 2c1 * g_{i-1} + g_{i-2}
            u64 cst = (i & 1) ? P2[j] : N2[j];
            u64 en = ffma2(cst, eC[j], eP[j]);
            u64 fn = ffma2(cst, fC[j], fP[j]);
            sE[j] = ffma2(cE, en, sE[j]);
            sF[j] = ffma2(cF, fn, sF[j]);
            eP[j] = eC[j]; eC[j] = en;
            fP[j] = fC[j]; fC[j] = fn;
        }
    }

    float bias = a0[0] * (1.0f / (2.0f * (float)NP));
    #pragma unroll
    for (int j = 0; j < 4; j++) {
        float2 vE = unpack2(sE[j]);
        float2 vF = unpack2(sF[j]);
        out[b * NP + tid + 256 * j] = (vE.x + vE.y) + (vF.x + vF.y) + bias;
    }
}

extern "C" void kernel_launch(void* const* d_in, const int* in_sizes, int n_in,
                              void* d_out, int out_size) {
    const float* x  = (const float*)d_in[0];
    const float* a  = (const float*)d_in[1];
    const float* b  = (const float*)d_in[2];
    const float* a0 = (const float*)d_in[3];
    float* out = (float*)d_out;

    // 16 rows x SU_STRIDE u64 = 131456 B dynamic smem for the x stage buffer.
    cudaFuncSetAttribute(k_gemm, cudaFuncAttributeMaxDynamicSharedMemorySize,
                         16 * SU_STRIDE * 8);

    k_gemm<<<128, 512, 16 * SU_STRIDE * 8>>>(x, a, b);
    k_fourier<<<BATCH, 256>>>(x, a0, out);
}

// round 5
// speedup vs baseline: 1.2355x; 1.0085x over previous
#include <cuda_runtime.h>

// Problem shape (fixed by dataset): x [512,1024] f32, a,b [1024,64,1] f32, a0 [1] f32
// out [512,1024] f32.
#define BATCH 512
#define NP    1024
#define NK    64

typedef unsigned long long u64;

// Scratch for the pa/pb GEMM results (device globals: allocation-free rule).
__device__ float g_pa[BATCH * NK];
__device__ float g_pb[BATCH * NK];

// ---------- packed f32x2 helpers (sm_103a FFMA2 path, PTX-only) ----------
__device__ __forceinline__ u64 ffma2(u64 a, u64 b, u64 c) {
    u64 d;
    asm("fma.rn.f32x2 %0, %1, %2, %3;" : "=l"(d) : "l"(a), "l"(b), "l"(c));
    return d;
}
__device__ __forceinline__ u64 fadd2(u64 a, u64 b) {
    u64 d;
    asm("add.rn.f32x2 %0, %1, %2;" : "=l"(d) : "l"(a), "l"(b));
    return d;
}
__device__ __forceinline__ u64 pack2(float lo, float hi) {
    u64 d;
    asm("mov.b64 %0, {%1, %2};"
        : "=l"(d) : "r"(__float_as_uint(lo)), "r"(__float_as_uint(hi)));
    return d;
}
__device__ __forceinline__ float2 unpack2(u64 v) {
    unsigned lo, hi;
    asm("mov.b64 {%0, %1}, %2;" : "=r"(lo), "=r"(hi) : "l"(v));
    return make_float2(__uint_as_float(lo), __uint_as_float(hi));
}

// ============================================================================
// Kernel 1: pa[b,k] = sum_p x[b,p]*a[p,k]; pb likewise.
//
// Grid = 64 b-tiles (8 rows) x 4 k-tiles = 256 blocks, 256 threads.
// smem 65.7KB -> 2 CTAs/SM: second CTA's mainloop overlaps first CTA's
// staging / reduction / barrier phases.
// Thread map: kq = tid&3 (k-quad), rg = (tid>>2)&1 (4 rows each),
// pg = tid>>3 (32 p-groups).
// x staged row-major in dynamic smem as (x,x) u64 pairs, row stride 1027
// (odd -> conflict-free LDS of 4 rows @ fixed p).
// Inner loop per p: 2x LDG.128 (a,b quad) + 4x LDS.64 (x rows) + 16 FFMA2.
// ============================================================================
#define SU_STRIDE 1027   // u64 units

__global__ __launch_bounds__(256, 2)
void k_gemm(const float* __restrict__ x,
            const float* __restrict__ a,
            const float* __restrict__ b) {
    extern __shared__ u64 su[];          // [8][SU_STRIDE] u64 = 65728 B; reused as red buf
    __shared__ u64 part[256];            // final reduction partials

    const int tid = threadIdx.x;
    const int bt  = blockIdx.x >> 2;
    const int kt  = blockIdx.x & 3;
    const int b0  = bt * 8;

    // ---- stage x row-major, duplicated: su[r*SU_STRIDE + p] = (x[b0+r][p], same) ----
    {
        const int r  = tid >> 5;         // warp id = row -> coalesced LDG
        const int pp = tid & 31;
        const float* xr = x + (size_t)(b0 + r) * NP;
        u64* dst = su + r * SU_STRIDE;
        #pragma unroll 8
        for (int j = 0; j < 32; j++) {
            int p = pp + 32 * j;
            float v = xr[p];
            dst[p] = pack2(v, v);
        }
    }
    __syncthreads();

    const int kq = tid & 3;              // k-quad within k-tile
    const int rg = (tid >> 2) & 1;       // row group (4 rows)
    const int pg = tid >> 3;             // p-group 0..31
    const int kcol  = kt * 4 + kq;       // ulonglong2 column index in a/b row
    const int rbase = rg * 4;

    const ulonglong2* a2 = (const ulonglong2*)a;  // row stride: 16 ulonglong2
    const ulonglong2* b2 = (const ulonglong2*)b;

    u64 acc[4][4];
    #pragma unroll
    for (int j = 0; j < 4; j++)
        #pragma unroll
        for (int c = 0; c < 4; c++) acc[j][c] = 0ull;

    #pragma unroll 4
    for (int p = pg; p < NP; p += 32) {
        ulonglong2 av = a2[p * 16 + kcol];
        ulonglong2 bv = b2[p * 16 + kcol];
        u64 x0 = su[(rbase + 0) * SU_STRIDE + p];
        u64 x1 = su[(rbase + 1) * SU_STRIDE + p];
        u64 x2 = su[(rbase + 2) * SU_STRIDE + p];
        u64 x3 = su[(rbase + 3) * SU_STRIDE + p];
        acc[0][0] = ffma2(x0, av.x, acc[0][0]);
        acc[0][1] = ffma2(x0, av.y, acc[0][1]);
        acc[0][2] = ffma2(x0, bv.x, acc[0][2]);
        acc[0][3] = ffma2(x0, bv.y, acc[0][3]);
        acc[1][0] = ffma2(x1, av.x, acc[1][0]);
        acc[1][1] = ffma2(x1, av.y, acc[1][1]);
        acc[1][2] = ffma2(x1, bv.x, acc[1][2]);
        acc[1][3] = ffma2(x1, bv.y, acc[1][3]);
        acc[2][0] = ffma2(x2, av.x, acc[2][0]);
        acc[2][1] = ffma2(x2, av.y, acc[2][1]);
        acc[2][2] = ffma2(x2, bv.x, acc[2][2]);
        acc[2][3] = ffma2(x2, bv.y, acc[2][3]);
        acc[3][0] = ffma2(x3, av.x, acc[3][0]);
        acc[3][1] = ffma2(x3, av.y, acc[3][1]);
        acc[3][2] = ffma2(x3, bv.x, acc[3][2]);
        acc[3][3] = ffma2(x3, bv.y, acc[3][3]);
    }

    __syncthreads();  // done reading su; reuse as reduction buffer

    // red[pg][local], local = r*16 + kq*4 + c  (r = row-in-tile 0..7) -> 128 locals
    u64* red = su;    // 32*128*8B = 32KB of the 64KB buffer
    #pragma unroll
    for (int j = 0; j < 4; j++)
        #pragma unroll
        for (int c = 0; c < 4; c++)
            red[pg * 128 + (rbase + j) * 16 + kq * 4 + c] = acc[j][c];
    __syncthreads();

    // Each thread sums 16 of the 32 p-groups for one local entry.
    const int local = tid & 127;
    const int half  = tid >> 7;       // 0: groups 0..15, 1: groups 16..31
    u64 v = red[(half * 16) * 128 + local];
    #pragma unroll
    for (int gg = 1; gg < 16; gg++)
        v = fadd2(v, red[(half * 16 + gg) * 128 + local]);
    part[tid] = v;
    __syncthreads();

    if (tid < 128) {
        u64 w = fadd2(part[tid], part[tid + 128]);
        const int r2  = tid >> 4;         // 0..7
        const int kq2 = (tid >> 2) & 3;
        const int c2  = tid & 3;
        float2 vv = unpack2(w);
        const int bb = b0 + r2;
        const int k0 = kt * 16 + kq2 * 4;
        if (c2 < 2) {
            *(float2*)&g_pa[bb * NK + k0 + 2 * c2] = vv;
        } else {
            *(float2*)&g_pb[bb * NK + k0 + 2 * (c2 - 2)] = vv;
        }
    }
}

// ============================================================================
// Kernel 2: out[b,p] = a0/(2P) + sum_k pa[b,k]*cos(k*th) + pb[b,k]*sin(k*th),
// th = (2pi/P)*x[b,p].
//
// Sign-folded Chebyshev (h_k = (-1)^floor(k/2)):
//   g_{k+1} = (-1)^k * 2*c1 * g_k + g_{k-1}   (pure FFMA2, alternating const)
// Two chains anchored at k=0 and k=32; MUFU __sincosf anchors.
//
// J=2 points per thread: 8 u64 of state per point -> ~50 regs total, fits the
// 64-reg budget of __launch_bounds__(256,4) WITHOUT spilling (the R4 J=4
// version needed 64 regs of state alone and serialized). 8 independent FMA
// chains/thread + 2 LDS feed 8 FFMA2 per unrolled iteration.
// ============================================================================
__global__ __launch_bounds__(256, 4)
void k_fourier(const float* __restrict__ x,
               const float* __restrict__ a0,
               float* __restrict__ out) {
    __shared__ u64 s_e[NK];  // h_k * (pa_k, pb_k) packed

    const int b   = blockIdx.x >> 1;
    const int ph  = (blockIdx.x & 1) * 512;
    const int tid = threadIdx.x;

    if (tid < NK) {
        float pa = g_pa[b * NK + tid];
        float pb = g_pb[b * NK + tid];
        float sgn = ((tid >> 1) & 1) ? -1.0f : 1.0f;   // h_k = (-1)^floor(k/2)
        s_e[tid] = pack2(sgn * pa, sgn * pb);
    }
    __syncthreads();

    const float TWO_PI_OVER_P = 0.006135923151542565f;  // 2*pi/1024

    u64 eP[2], eC[2], fP[2], fC[2], sE[2], sF[2], P2[2], N2[2];

    u64 ce0 = s_e[0], ce1 = s_e[1], cf0 = s_e[32], cf1 = s_e[33];

    #pragma unroll
    for (int j = 0; j < 2; j++) {
        float xv = x[b * NP + ph + tid + 256 * j];
        float th = TWO_PI_OVER_P * xv;
        float s1, c1, s32v, c32v;
        __sincosf(th, &s1, &c1);
        __sincosf(32.0f * th, &s32v, &c32v);

        float t2 = 2.0f * c1;
        P2[j] = pack2(t2, t2);
        N2[j] = pack2(-t2, -t2);

        eP[j] = pack2(1.0f, 0.0f);                 // g_0
        eC[j] = pack2(c1, s1);                     // g_1 (h_1 = +1)
        float c33 = fmaf(c32v, c1, -s32v * s1);
        float s33 = fmaf(s32v, c1,  c32v * s1);
        fP[j] = pack2(c32v, s32v);                 // f_0 (h_32 = +1)
        fC[j] = pack2(c33, s33);                   // f_1 (h_33 = +1)

        sE[j] = ffma2(ce0, eP[j], 0ull);
        sE[j] = ffma2(ce1, eC[j], sE[j]);
        sF[j] = ffma2(cf0, fP[j], 0ull);
        sF[j] = ffma2(cf1, fC[j], sF[j]);
    }

    #pragma unroll
    for (int i = 2; i < 32; i++) {
        u64 cE = s_e[i];
        u64 cF = s_e[32 + i];
        #pragma unroll
        for (int j = 0; j < 2; j++) {
            // g_i = (-1)^{i-1} * 2c1 * g_{i-1} + g_{i-2}
            u64 cst = (i & 1) ? P2[j] : N2[j];
            u64 en = ffma2(cst, eC[j], eP[j]);
            u64 fn = ffma2(cst, fC[j], fP[j]);
            sE[j] = ffma2(cE, en, sE[j]);
            sF[j] = ffma2(cF, fn, sF[j]);
            eP[j] = eC[j]; eC[j] = en;
            fP[j] = fC[j]; fC[j] = fn;
        }
    }

    float bias = a0[0] * (1.0f / (2.0f * (float)NP));
    #pragma unroll
    for (int j = 0; j < 2; j++) {
        float2 vE = unpack2(sE[j]);
        float2 vF = unpack2(sF[j]);
        out[b * NP + ph + tid + 256 * j] = (vE.x + vE.y) + (vF.x + vF.y) + bias;
    }
}

extern "C" void kernel_launch(void* const* d_in, const int* in_sizes, int n_in,
                              void* d_out, int out_size) {
    const float* x  = (const float*)d_in[0];
    const float* a  = (const float*)d_in[1];
    const float* b  = (const float*)d_in[2];
    const float* a0 = (const float*)d_in[3];
    float* out = (float*)d_out;

    // 8 rows x SU_STRIDE u64 = 65728 B dynamic smem for the x stage buffer.
    cudaFuncSetAttribute(k_gemm, cudaFuncAttributeMaxDynamicSharedMemorySize,
                         8 * SU_STRIDE * 8);

    k_gemm<<<256, 256, 8 * SU_STRIDE * 8>>>(x, a, b);
    k_fourier<<<BATCH * 2, 256>>>(x, a0, out);
}